// round 3
// baseline (speedup 1.0000x reference)
#include <cuda_runtime.h>
#include <cuda_bf16.h>

// IoU_31336081391713: elementwise YOLO IoU.
// Inputs (metadata order): cell_nos [N,2] int32, output [N,5,5] f32, target [N,5] f32.
// Output: IoU [N,5] f32.
// HBM-bound streaming kernel: smem-staged, float4-coalesced loads & stores.

#define YI 20.0f
#define BPB 256           // boxes per block == threads per block
#define NA 5              // anchors
#define OUT_F (BPB * 25)  // 6400 floats of `output` per block
#define TGT_F (BPB * 5)   // 1280 floats of `target` per block
#define RES_F (BPB * 5)   // 1280 floats of result per block
#define CELL_I (BPB * 2)  // 512 ints of cell_nos per block

__global__ __launch_bounds__(BPB) void iou_kernel(
    const int*   __restrict__ g_cell,
    const float* __restrict__ g_out,
    const float* __restrict__ g_tgt,
    float*       __restrict__ g_res,
    int n_boxes)
{
    __shared__ float s_out[OUT_F];
    __shared__ float s_tgt[TGT_F];
    __shared__ float s_res[RES_F];
    __shared__ int   s_cell[CELL_I];

    const int tid = threadIdx.x;
    const int b0  = blockIdx.x * BPB;          // first box of this block
    const bool full = (b0 + BPB) <= n_boxes;   // full-tile fast path

    if (full) {
        // ---- coalesced float4 staging (all chunk bases are 128B-aligned) ----
        const float4* go4 = reinterpret_cast<const float4*>(g_out + (size_t)b0 * 25);
        #pragma unroll
        for (int i = tid; i < OUT_F / 4; i += BPB) reinterpret_cast<float4*>(s_out)[i] = go4[i];

        const float4* gt4 = reinterpret_cast<const float4*>(g_tgt + (size_t)b0 * 5);
        #pragma unroll
        for (int i = tid; i < TGT_F / 4; i += BPB) reinterpret_cast<float4*>(s_tgt)[i] = gt4[i];

        const int4* gc4 = reinterpret_cast<const int4*>(g_cell + (size_t)b0 * 2);
        if (tid < CELL_I / 4) reinterpret_cast<int4*>(s_cell)[tid] = gc4[tid];
    } else {
        // ---- guarded scalar tail path ----
        const int nb = n_boxes - b0;  // boxes in this (last) block, 0 < nb < BPB
        for (int i = tid; i < nb * 25; i += BPB) s_out[i]  = g_out[(size_t)b0 * 25 + i];
        for (int i = tid; i < nb * 5;  i += BPB) s_tgt[i]  = g_tgt[(size_t)b0 * 5  + i];
        for (int i = tid; i < nb * 2;  i += BPB) s_cell[i] = g_cell[(size_t)b0 * 2 + i];
    }
    __syncthreads();

    const bool active = (b0 + tid) < n_boxes;
    if (active) {
        // per-box values (stride-25 / stride-5 smem reads are conflict-free: odd stride)
        const float ci = (float)s_cell[tid * 2 + 0] * YI + YI * 0.5f;  // cell_i_center
        const float cj = (float)s_cell[tid * 2 + 1] * YI + YI * 0.5f;  // cell_j_center

        // ground-truth box (match reference arithmetic order exactly)
        const float* t = s_tgt + tid * 5;
        const float hg  = t[3] * YI;
        const float wg  = t[4] * YI;
        const float xcg = ci + t[1] * YI;
        const float ycg = cj + t[2] * YI;
        const float gx1 = ycg - wg * 0.5f;
        const float gy1 = xcg - hg * 0.5f;
        const float gx2 = ycg + wg * 0.5f;
        const float gy2 = xcg + hg * 0.5f;
        const float area_g = (gx2 - gx1) * (gy2 - gy1);

        const float* o = s_out + tid * 25;
        #pragma unroll
        for (int a = 0; a < NA; a++) {
            const float* p = o + a * 5;
            const float h  = p[3] * YI;
            const float w  = p[4] * YI;
            const float xc = ci + p[1] * YI;
            const float yc = cj + p[2] * YI;
            const float px1 = yc - w * 0.5f;
            const float py1 = xc - h * 0.5f;
            const float px2 = yc + w * 0.5f;
            const float py2 = xc + h * 0.5f;
            const float area_p = (px2 - px1) * (py2 - py1);

            const float ltx = fmaxf(px1, gx1);
            const float lty = fmaxf(py1, gy1);
            const float rbx = fminf(px2, gx2);
            const float rby = fminf(py2, gy2);
            const float wx  = fmaxf(rbx - ltx, 0.0f);
            const float wy  = fmaxf(rby - lty, 0.0f);
            const float inter = wx * wy;
            const float uni   = area_p + area_g - inter;
            s_res[tid * 5 + a] = inter / uni;
        }
    }
    __syncthreads();

    if (full) {
        float4* gr4 = reinterpret_cast<float4*>(g_res + (size_t)b0 * 5);
        #pragma unroll
        for (int i = tid; i < RES_F / 4; i += BPB) gr4[i] = reinterpret_cast<const float4*>(s_res)[i];
    } else {
        const int nb = n_boxes - b0;
        for (int i = tid; i < nb * 5; i += BPB) g_res[(size_t)b0 * 5 + i] = s_res[i];
    }
}

extern "C" void kernel_launch(void* const* d_in, const int* in_sizes, int n_in,
                              void* d_out, int out_size) {
    const int*   cell = (const int*)d_in[0];    // [N,2] int32
    const float* outp = (const float*)d_in[1];  // [N,5,5] f32
    const float* tgt  = (const float*)d_in[2];  // [N,5] f32
    float*       res  = (float*)d_out;          // [N,5] f32

    const int n_boxes = in_sizes[0] / 2;
    const int grid = (n_boxes + BPB - 1) / BPB;
    iou_kernel<<<grid, BPB>>>(cell, outp, tgt, res, n_boxes);
}

// round 5
// speedup vs baseline: 1.1838x; 1.1838x over previous
#include <cuda_runtime.h>
#include <cuda_bf16.h>

// IoU_31336081391713: elementwise YOLO IoU.
// Inputs: cell_nos [N,2] i32, output [N,5,5] f32, target [N,5] f32 -> IoU [N,5] f32.
// Persistent-block, cp.async double-buffered streaming kernel (DRAM-bound).

#define YI 20.0f
#define TILE 128          // boxes per tile == threads per block
#define THREADS 128
#define NA 5
#define OUT_F (TILE * 25) // 3200 floats
#define TGT_F (TILE * 5)  // 640 floats
#define CELL_I (TILE * 2) // 256 ints

__device__ __forceinline__ void cpa16(void* smem, const void* gmem) {
    unsigned s = (unsigned)__cvta_generic_to_shared(smem);
    asm volatile("cp.async.cg.shared.global [%0], [%1], 16;\n" :: "r"(s), "l"(gmem));
}
#define CP_COMMIT() asm volatile("cp.async.commit_group;\n" ::: "memory")
#define CP_WAIT1()  asm volatile("cp.async.wait_group 1;\n" ::: "memory")

struct Buffers {
    float s_out[2][OUT_F];
    float s_tgt[2][TGT_F];
    int   s_cell[2][CELL_I];
    float s_res[TGT_F];
};

__device__ __forceinline__ void prefetch_tile(
    Buffers& B, int st, int tid, size_t b0, int nb,
    const int* __restrict__ g_cell,
    const float* __restrict__ g_out,
    const float* __restrict__ g_tgt)
{
    if (nb == TILE) {
        const float4* go4 = reinterpret_cast<const float4*>(g_out + b0 * 25);
        #pragma unroll
        for (int i = tid; i < OUT_F / 4; i += THREADS) cpa16(&B.s_out[st][i * 4], go4 + i);
        const float4* gt4 = reinterpret_cast<const float4*>(g_tgt + b0 * 5);
        #pragma unroll
        for (int i = tid; i < TGT_F / 4; i += THREADS) cpa16(&B.s_tgt[st][i * 4], gt4 + i);
        const int4* gc4 = reinterpret_cast<const int4*>(g_cell + b0 * 2);
        if (tid < CELL_I / 4) cpa16(&B.s_cell[st][tid * 4], gc4 + tid);
    } else {
        // guarded scalar tail (not hit for N=4M; kept for generality)
        for (int i = tid; i < nb * 25; i += THREADS) B.s_out[st][i]  = g_out[b0 * 25 + i];
        for (int i = tid; i < nb * 5;  i += THREADS) B.s_tgt[st][i]  = g_tgt[b0 * 5 + i];
        for (int i = tid; i < nb * 2;  i += THREADS) B.s_cell[st][i] = g_cell[b0 * 2 + i];
    }
}

__global__ __launch_bounds__(THREADS) void iou_kernel(
    const int*   __restrict__ g_cell,
    const float* __restrict__ g_out,
    const float* __restrict__ g_tgt,
    float*       __restrict__ g_res,
    int n_boxes, int n_tiles)
{
    __shared__ Buffers B;

    const int tid = threadIdx.x;
    const int G   = gridDim.x;

    // prologue: stage first tile into buffer 0
    {
        const int it = blockIdx.x;
        if (it < n_tiles) {
            const size_t b0 = (size_t)it * TILE;
            int nb = n_boxes - (int)b0; if (nb > TILE) nb = TILE;
            prefetch_tile(B, 0, tid, b0, nb, g_cell, g_out, g_tgt);
        }
    }
    CP_COMMIT();

    int st = 0;
    for (int it = blockIdx.x; it < n_tiles; it += G, st ^= 1) {
        // stage next tile into the other buffer (overlaps wait+compute+store)
        const int nt = it + G;
        if (nt < n_tiles) {
            const size_t b0n = (size_t)nt * TILE;
            int nbn = n_boxes - (int)b0n; if (nbn > TILE) nbn = TILE;
            prefetch_tile(B, st ^ 1, tid, b0n, nbn, g_cell, g_out, g_tgt);
        }
        CP_COMMIT();
        CP_WAIT1();           // current buffer's group is complete
        __syncthreads();      // also orders s_res reuse across iterations

        const size_t b0 = (size_t)it * TILE;
        int nb = n_boxes - (int)b0; if (nb > TILE) nb = TILE;

        if (tid < nb) {
            const float ci = (float)B.s_cell[st][tid * 2 + 0] * YI + YI * 0.5f;
            const float cj = (float)B.s_cell[st][tid * 2 + 1] * YI + YI * 0.5f;

            const float* t = &B.s_tgt[st][tid * 5];
            const float hg  = t[3] * YI;
            const float wg  = t[4] * YI;
            const float xcg = ci + t[1] * YI;
            const float ycg = cj + t[2] * YI;
            const float gx1 = ycg - wg * 0.5f;
            const float gy1 = xcg - hg * 0.5f;
            const float gx2 = ycg + wg * 0.5f;
            const float gy2 = xcg + hg * 0.5f;
            const float area_g = (gx2 - gx1) * (gy2 - gy1);

            const float* o = &B.s_out[st][tid * 25];
            #pragma unroll
            for (int a = 0; a < NA; a++) {
                const float* p = o + a * 5;
                const float h  = p[3] * YI;
                const float w  = p[4] * YI;
                const float xc = ci + p[1] * YI;
                const float yc = cj + p[2] * YI;
                const float px1 = yc - w * 0.5f;
                const float py1 = xc - h * 0.5f;
                const float px2 = yc + w * 0.5f;
                const float py2 = xc + h * 0.5f;
                const float area_p = (px2 - px1) * (py2 - py1);

                const float ltx = fmaxf(px1, gx1);
                const float lty = fmaxf(py1, gy1);
                const float rbx = fminf(px2, gx2);
                const float rby = fminf(py2, gy2);
                const float wx  = fmaxf(rbx - ltx, 0.0f);
                const float wy  = fmaxf(rby - lty, 0.0f);
                const float inter = wx * wy;
                const float uni   = area_p + area_g - inter;
                B.s_res[tid * 5 + a] = inter / uni;
            }
        }
        __syncthreads();

        if (nb == TILE) {
            float4* gr4 = reinterpret_cast<float4*>(g_res + b0 * 5);
            #pragma unroll
            for (int i = tid; i < TGT_F / 4; i += THREADS)
                __stcs(gr4 + i, reinterpret_cast<const float4*>(B.s_res)[i]);
        } else {
            for (int i = tid; i < nb * 5; i += THREADS) g_res[b0 * 5 + i] = B.s_res[i];
        }
        // next iteration's first __syncthreads orders s_res/buffer reuse
    }
}

extern "C" void kernel_launch(void* const* d_in, const int* in_sizes, int n_in,
                              void* d_out, int out_size) {
    const int*   cell = (const int*)d_in[0];
    const float* outp = (const float*)d_in[1];
    const float* tgt  = (const float*)d_in[2];
    float*       res  = (float*)d_out;

    const int n_boxes = in_sizes[0] / 2;
    const int n_tiles = (n_boxes + TILE - 1) / TILE;
    int grid = 152 * 6;               // persistent: 6 blocks/SM * 152 SMs
    if (grid > n_tiles) grid = n_tiles;
    iou_kernel<<<grid, THREADS>>>(cell, outp, tgt, res, n_boxes, n_tiles);
}